// round 7
// baseline (speedup 1.0000x reference)
#include <cuda_runtime.h>
#include <cuda_bf16.h>
#include <mma.h>
#include <cstdint>

using namespace nvcuda;

#define NN 100000
#define NE 1600000
#define TILES ((NN + 127) / 128)   // 782

// ---------------- scratch (device globals; no allocation allowed) ----------------
__device__ __align__(16) float g_aggr[(size_t)NN * 128];
__device__ __align__(16) float g_h[(size_t)NN * 128];
__device__ int g_deg[NN];          // zero at start of every call (tail-zeroed)
__device__ int g_rowStart[NN];
__device__ int g_cursor[NN];
__device__ int g_srcIdx[NE];
__device__ int g_ctr;              // zero at start of every call (tail-zeroed)
// Pre-split weight images: [half][hi/lo][k 0..127][n 0..NP)
__device__ __align__(16) unsigned short g_Bimg1[2 * 2 * 128 * 136];  // layer1 NP=136
__device__ __align__(16) unsigned short g_Bimg2[2 * 2 * 128 * 72];   // layer2 NP=72

__device__ __forceinline__ void split2(float a, float b, uint32_t& h, uint32_t& l) {
    __nv_bfloat162 hb = __floats2bfloat162_rn(a, b);
    float2 hf = __bfloat1622float2(hb);
    __nv_bfloat162 lb = __floats2bfloat162_rn(a - hf.x, b - hf.y);
    h = *reinterpret_cast<uint32_t*>(&hb);
    l = *reinterpret_cast<uint32_t*>(&lb);
}

// ---------------- CSR build (3 launches; segments unordered -- max is order-insensitive) ----
__global__ void k_count(const int* __restrict__ edst) {
    int i = blockIdx.x * blockDim.x + threadIdx.x;
    if (i < NE) atomicAdd(&g_deg[edst[i]], 1);
}
// per-block inclusive scan + one atomicAdd for the block base; rowStart = base + excl
__global__ void __launch_bounds__(256) k_offsets() {
    __shared__ int s[256];
    __shared__ int base;
    int t = threadIdx.x;
    int i = blockIdx.x * 256 + t;
    int d = (i < NN) ? g_deg[i] : 0;
    s[t] = d;
    __syncthreads();
#pragma unroll
    for (int off = 1; off < 256; off <<= 1) {
        int x = (t >= off) ? s[t - off] : 0;
        __syncthreads();
        s[t] += x;
        __syncthreads();
    }
    if (t == 255) base = atomicAdd(&g_ctr, s[255]);
    __syncthreads();
    if (i < NN) {
        int r = base + s[t] - d;
        g_rowStart[i] = r;
        g_cursor[i] = r;
    }
}
__global__ void k_fill(const int* __restrict__ esrc, const int* __restrict__ edst) {
    int i = blockIdx.x * blockDim.x + threadIdx.x;
    if (i < NE) {
        int p = atomicAdd(&g_cursor[edst[i]], 1);
        g_srcIdx[p] = esrc[i];
    }
}
// restore invariant: g_deg = 0, g_ctr = 0 for the next call (device globals start zeroed)
__global__ void k_tail_zero() {
    int i = blockIdx.x * blockDim.x + threadIdx.x;
    if (i < NN) g_deg[i] = 0;
    if (i == 0) g_ctr = 0;
}

// ---------------- aggregation: warp per node, gather-max over CSR row ----------------
__device__ __forceinline__ float4 max4(float4 a, float4 b) {
    return make_float4(fmaxf(a.x, b.x), fmaxf(a.y, b.y), fmaxf(a.z, b.z), fmaxf(a.w, b.w));
}
template<bool USE_H>
__global__ void __launch_bounds__(256) k_aggr(const float* __restrict__ xin) {
    int w = (blockIdx.x * blockDim.x + threadIdx.x) >> 5;
    if (w >= NN) return;
    int lane = threadIdx.x & 31;
    const float* feat = USE_H ? g_h : xin;
    int beg = g_rowStart[w];
    int end = beg + g_deg[w];
    const float NEG = __int_as_float(0xff800000);
    float4 m = make_float4(NEG, NEG, NEG, NEG);
    int e = beg;
    for (; e + 4 <= end; e += 4) {
        int s0 = g_srcIdx[e + 0], s1 = g_srcIdx[e + 1];
        int s2 = g_srcIdx[e + 2], s3 = g_srcIdx[e + 3];
        float4 v0 = *(const float4*)(feat + (size_t)s0 * 128 + lane * 4);
        float4 v1 = *(const float4*)(feat + (size_t)s1 * 128 + lane * 4);
        float4 v2 = *(const float4*)(feat + (size_t)s2 * 128 + lane * 4);
        float4 v3 = *(const float4*)(feat + (size_t)s3 * 128 + lane * 4);
        m = max4(m, max4(max4(v0, v1), max4(v2, v3)));
    }
    for (; e < end; e++) {
        float4 v0 = *(const float4*)(feat + (size_t)g_srcIdx[e] * 128 + lane * 4);
        m = max4(m, v0);
    }
    if (beg == end) m = make_float4(0.f, 0.f, 0.f, 0.f);
    *(float4*)(g_aggr + (size_t)w * 128 + lane * 4) = m;
}

// ---------------- weight prep: split-bf16, B[k][n] padded row-major images ----------------
template<int COUT>
__global__ void k_prepB(const float* __restrict__ Wl, const float* __restrict__ Wr,
                        unsigned short* __restrict__ dst) {
    constexpr int NP = COUT + 8;
    int idx = blockIdx.x * blockDim.x + threadIdx.x;
    if (idx >= 2 * 128 * COUT) return;
    int half = idx / (128 * COUT);
    int rem = idx - half * 128 * COUT;
    int k = rem / COUT;
    int n = rem - k * COUT;
    float f = (half ? Wr : Wl)[k * COUT + n];
    __nv_bfloat16 hb = __float2bfloat16(f);
    __nv_bfloat16 lb = __float2bfloat16(f - __bfloat162float(hb));
    dst[((size_t)(half * 2 + 0) * 128 + k) * NP + n] = *reinterpret_cast<unsigned short*>(&hb);
    dst[((size_t)(half * 2 + 1) * 128 + k) * NP + n] = *reinterpret_cast<unsigned short*>(&lb);
}

// ---------------- persistent wmma split-bf16 fused SAGE GEMM ----------------
// B (all 4 images) loaded ONCE per CTA into smem; CTA loops over 128-row tiles.
// 16 warps: 4(m) x 4(n); warp tile 32 x COUT/4. Terms: AhBh + AhBl + AlBh.
template<int COUT, bool L1>
__global__ void __launch_bounds__(512) k_gemm_wm(const float* __restrict__ xin,
                                                 const unsigned short* __restrict__ Bimg,
                                                 const float* __restrict__ bias,
                                                 float* __restrict__ outp) {
    constexpr int NP = COUT + 8;
    constexpr int AP = 136;
    constexpr int WN = COUT / 4;            // L1:32, L2:16
    constexpr int NT = WN / 16;             // L1:2,  L2:1
    constexpr int EW = WN + 2;              // epilogue stride (floats)
    extern __shared__ char smem[];
    __nv_bfloat16* Ah = (__nv_bfloat16*)smem;
    __nv_bfloat16* Al = Ah + 128 * AP;
    __nv_bfloat16* B0 = Al + 128 * AP;      // [half][hi/lo] images, each 128*NP

    int tid = threadIdx.x, wid = tid >> 5, lane = tid & 31;
    int wm = wid & 3, wn = wid >> 2;

    // load all 4 B images once
    {
        const uint4* src = (const uint4*)Bimg;
        uint4* dst = (uint4*)B0;
        const int n4 = 4 * 128 * NP * 2 / 16;
        for (int i = tid; i < n4; i += 512) dst[i] = src[i];
    }

    const float* rootSrc = L1 ? xin : g_h;
    float* out = L1 ? g_h : outp;
    int r = tid >> 2, kq = (tid & 3) << 5;  // staging: row 0..127, k-quarter 0/32/64/96

    for (int tile = blockIdx.x; tile < TILES; tile += gridDim.x) {
        int rowBase = tile * 128;
        int grow = rowBase + r;

        wmma::fragment<wmma::accumulator, 16, 16, 16, float> acc[2][NT];
#pragma unroll
        for (int i = 0; i < 2; i++)
#pragma unroll
            for (int j = 0; j < NT; j++) wmma::fill_fragment(acc[i][j], 0.0f);

#pragma unroll
        for (int half = 0; half < 2; half++) {
            const float* Asrc = half ? rootSrc : g_aggr;
            const float4* srcv = (grow < NN) ? (const float4*)(Asrc + (size_t)grow * 128 + kq) : nullptr;
            __syncthreads();   // prior tile epilogue / prior half MMA done before restaging A
#pragma unroll
            for (int i = 0; i < 8; i++) {
                float4 v = srcv ? srcv[i] : make_float4(0.f, 0.f, 0.f, 0.f);
                uint32_t h0, l0, h1, l1;
                split2(v.x, v.y, h0, l0);
                split2(v.z, v.w, h1, l1);
                *(uint2*)((unsigned short*)Ah + (size_t)r * AP + kq + i * 4) = make_uint2(h0, h1);
                *(uint2*)((unsigned short*)Al + (size_t)r * AP + kq + i * 4) = make_uint2(l0, l1);
            }
            __syncthreads();

            const __nv_bfloat16* Bh = B0 + (size_t)(half * 2 + 0) * 128 * NP;
            const __nv_bfloat16* Bl = B0 + (size_t)(half * 2 + 1) * 128 * NP;
#pragma unroll
            for (int ks = 0; ks < 8; ks++) {
                int k0 = ks * 16;
                wmma::fragment<wmma::matrix_a, 16, 16, 16, __nv_bfloat16, wmma::row_major> fa_h[2], fa_l[2];
#pragma unroll
                for (int mt = 0; mt < 2; mt++) {
                    wmma::load_matrix_sync(fa_h[mt], Ah + (size_t)(wm * 32 + mt * 16) * AP + k0, AP);
                    wmma::load_matrix_sync(fa_l[mt], Al + (size_t)(wm * 32 + mt * 16) * AP + k0, AP);
                }
#pragma unroll
                for (int nt = 0; nt < NT; nt++) {
                    wmma::fragment<wmma::matrix_b, 16, 16, 16, __nv_bfloat16, wmma::row_major> fb_h, fb_l;
                    wmma::load_matrix_sync(fb_h, Bh + (size_t)k0 * NP + wn * WN + nt * 16, NP);
                    wmma::load_matrix_sync(fb_l, Bl + (size_t)k0 * NP + wn * WN + nt * 16, NP);
#pragma unroll
                    for (int mt = 0; mt < 2; mt++) wmma::mma_sync(acc[mt][nt], fa_h[mt], fb_h, acc[mt][nt]);
#pragma unroll
                    for (int mt = 0; mt < 2; mt++) wmma::mma_sync(acc[mt][nt], fa_h[mt], fb_l, acc[mt][nt]);
#pragma unroll
                    for (int mt = 0; mt < 2; mt++) wmma::mma_sync(acc[mt][nt], fa_l[mt], fb_h, acc[mt][nt]);
                }
            }
        }
        __syncthreads();   // MMA reads of A done before epilogue reuses the A region

        // epilogue: bounce fragments through the A region, fuse bias+ReLU
        float* bw = (float*)Ah + (size_t)wid * 32 * EW;
#pragma unroll
        for (int mt = 0; mt < 2; mt++)
#pragma unroll
            for (int nt = 0; nt < NT; nt++)
                wmma::store_matrix_sync(bw + mt * 16 * EW + nt * 16, acc[mt][nt], EW, wmma::mem_row_major);
        __syncwarp();

        int orow = rowBase + wm * 32 + lane;
        if (orow < NN) {
            float* op = out + (size_t)orow * COUT + wn * WN;
            const float* br = bw + (size_t)lane * EW;
#pragma unroll
            for (int c = 0; c < WN; c += 4) {
                float4 v = make_float4(br[c], br[c + 1], br[c + 2], br[c + 3]);
                v.x += bias[wn * WN + c + 0];
                v.y += bias[wn * WN + c + 1];
                v.z += bias[wn * WN + c + 2];
                v.w += bias[wn * WN + c + 3];
                if (L1) {
                    v.x = fmaxf(v.x, 0.f); v.y = fmaxf(v.y, 0.f);
                    v.z = fmaxf(v.z, 0.f); v.w = fmaxf(v.w, 0.f);
                }
                *(float4*)(op + c) = v;
            }
        }
    }
}

extern "C" void kernel_launch(void* const* d_in, const int* in_sizes, int n_in,
                              void* d_out, int out_size) {
    const float* x   = (const float*)d_in[0];
    const int*   ei  = (const int*)d_in[1];
    const float* W1l = (const float*)d_in[2];
    const float* b1  = (const float*)d_in[3];
    const float* W1r = (const float*)d_in[4];
    const float* W2l = (const float*)d_in[5];
    const float* b2  = (const float*)d_in[6];
    const float* W2r = (const float*)d_in[7];
    float*       out = (float*)d_out;

    const int* esrc = ei;
    const int* edst = ei + NE;

    const int edgeBlocks = (NE + 255) / 256;
    const int nodeBlocks = (NN + 255) / 256;
    const int aggrBlocks = (NN * 32 + 255) / 256;

    int nsm = 148;
    cudaDeviceGetAttribute(&nsm, cudaDevAttrMultiProcessorCount, 0);

    // dynamic SMEM: A(2 x 128 x 136) + B(4 x 128 x NP), bf16
    const int SMEM1 = (2 * 128 * 136 + 4 * 128 * 136) * 2;   // 208,896 B
    const int SMEM2 = (2 * 128 * 136 + 4 * 128 * 72) * 2;    // 143,360 B
    cudaFuncSetAttribute(k_gemm_wm<128, true>, cudaFuncAttributeMaxDynamicSharedMemorySize, SMEM1);
    cudaFuncSetAttribute(k_gemm_wm<64, false>, cudaFuncAttributeMaxDynamicSharedMemorySize, SMEM2);

    unsigned short* bimg1;
    unsigned short* bimg2;
    cudaGetSymbolAddress((void**)&bimg1, g_Bimg1);
    cudaGetSymbolAddress((void**)&bimg2, g_Bimg2);

    // CSR build (g_deg / g_ctr are zero: zero-init at load + tail-zero every call)
    k_count<<<edgeBlocks, 256>>>(edst);                       // launch 1
    k_offsets<<<nodeBlocks, 256>>>();                         // launch 2
    k_fill<<<edgeBlocks, 256>>>(esrc, edst);                  // launch 3

    // Layer 1 aggregation -- launch #4 (ncu sample slot)
    k_aggr<false><<<aggrBlocks, 256>>>(x);                    // launch 4

    // weight prep
    k_prepB<128><<<(2 * 128 * 128 + 255) / 256, 256>>>(W1l, W1r, bimg1);   // launch 5
    k_prepB<64><<<(2 * 128 * 64 + 255) / 256, 256>>>(W2l, W2r, bimg2);     // launch 6

    // Layer 1 GEMM, layer 2
    k_gemm_wm<128, true><<<nsm, 512, SMEM1>>>(x, bimg1, b1, nullptr);      // launch 7
    k_aggr<true><<<aggrBlocks, 256>>>(nullptr);                             // launch 8
    k_gemm_wm<64, false><<<nsm, 512, SMEM2>>>(nullptr, bimg2, b2, out);     // launch 9

    // restore invariant for next call
    k_tail_zero<<<nodeBlocks, 256>>>();                                     // launch 10
}